// round 15
// baseline (speedup 1.0000x reference)
#include <cuda_runtime.h>
#include <cuda_fp16.h>
#include <cstdint>
#include <math.h>

#define DI __device__ __forceinline__

#define NN 256
#define HH 1024
#define EE 512
#define VV 32000
#define KXT 2560
#define PRED_OFF 8192000
#define HC (NN*HH)

__device__ __align__(16) __half g_Xh[NN * KXT];
__device__ __align__(16) float g_gates[4 * NN * 4096];
__device__ __align__(16) __half g_h1h[NN * HH];

// ---------- helpers ----------
DI uint32_t smem_u32(const void* p) {
    uint32_t a;
    asm("{ .reg .u64 t; cvta.to.shared.u64 t, %1; cvt.u32.u64 %0, t; }" : "=r"(a) : "l"(p));
    return a;
}
DI void cpa16(uint32_t s, const void* g) {
    asm volatile("cp.async.cg.shared.global [%0], [%1], 16;" :: "r"(s), "l"(g));
}
DI uint32_t lds_u32(uint32_t a) {
    uint32_t x;
    asm volatile("ld.shared.b32 %0, [%1];" : "=r"(x) : "r"(a));
    return x;
}
DI float2 lds_f2(uint32_t a) {
    float2 v;
    asm volatile("ld.shared.v2.f32 {%0,%1}, [%2];" : "=f"(v.x), "=f"(v.y) : "r"(a));
    return v;
}
DI uint32_t pack_h2(float2 v) {
    __half2 h = __floats2half2_rn(v.x, v.y);
    return *(uint32_t*)&h;
}
DI uint32_t pack2(float x, float y) {
    __half2 h = __floats2half2_rn(x, y);
    return *(uint32_t*)&h;
}
DI void mma16(float c[4], const uint32_t a[4], uint32_t b0, uint32_t b1) {
    asm volatile(
        "mma.sync.aligned.m16n8k16.row.col.f32.f16.f16.f32 "
        "{%0,%1,%2,%3}, {%4,%5,%6,%7}, {%8,%9}, {%0,%1,%2,%3};"
        : "+f"(c[0]), "+f"(c[1]), "+f"(c[2]), "+f"(c[3])
        : "r"(a[0]), "r"(a[1]), "r"(a[2]), "r"(a[3]), "r"(b0), "r"(b1));
}

// ---------- B-source functors (fp32 gmem) ----------
struct BFc {
    const float* w;
    DI const float* ptr(int r, int k) const { return w + (size_t)r * HH + k; }
};
struct BGates {
    const float* wih;
    const float* whh;
    DI const float* ptr(int r, int k) const {
        return (k < 1536) ? wih + (size_t)r * 1536 + k
                          : whh + (size_t)r * 1024 + (k - 1536);
    }
};

// =======================================================================
// fp16 GEMM core: CTA 256x128, 512 thr = 16 warps of 64x32 (4x4 grid),
// ktile 64 (4 k16 steps), 3 stages, ONE barrier per iteration.
// A fp16: 256 rows x 144B (128B data + 16B pad -> conflict-free frags).
// B fp32: 128 rows x 256B, 32B-unit XOR swizzle (unit u at u^(r&7)).
// =======================================================================
#define G_AS 36864               // 256 * 144
#define G_STAGE (G_AS + 32768)   // + B 128 * 256
#define G_SMEM (3 * G_STAGE)     // 208896

template <class BS>
DI void g_load(uint32_t As, uint32_t Bs, const __half* Ah, int lda, BS bs,
               int ntb, int kg, int t) {
#pragma unroll
    for (int i = 0; i < 4; i++) {  // A: 256 rows x 8 chunks of 16B = 2048
        int idx = i * 512 + t, r = idx >> 3, c = idx & 7;
        cpa16(As + (uint32_t)(r * 144 + c * 16),
              (const char*)Ah + (size_t)r * lda * 2 + (size_t)kg * 2 + c * 16);
    }
#pragma unroll
    for (int i = 0; i < 4; i++) {  // B: 128 rows x 16 chunks of 16B = 2048
        int idx = i * 512 + t, r = idx >> 4, cc = idx & 15;
        cpa16(Bs + (uint32_t)(r * 256 + (((cc >> 1) ^ (r & 7)) << 5) + (cc & 1) * 16),
              bs.ptr(ntb + r, kg + cc * 4));
    }
}

DI void g_frag(uint32_t As, uint32_t Bs, int wm, int wn, int gid, int tid,
               int s, uint32_t a[4][4], uint32_t b[4][2]) {
#pragma unroll
    for (int mf = 0; mf < 4; mf++) {
        uint32_t ro = As + (uint32_t)((wm + mf * 16 + gid) * 144 + s * 32 + tid * 4);
        a[mf][0] = lds_u32(ro);
        a[mf][1] = lds_u32(ro + 8 * 144);
        a[mf][2] = lds_u32(ro + 16);
        a[mf][3] = lds_u32(ro + 8 * 144 + 16);
    }
    const uint32_t c0 = (uint32_t)((((2 * s) ^ gid) << 5) + tid * 8);
    const uint32_t c1 = (uint32_t)((((2 * s + 1) ^ gid) << 5) + tid * 8);
#pragma unroll
    for (int nf = 0; nf < 4; nf++) {
        uint32_t ro = Bs + (uint32_t)((wn + nf * 8 + gid) * 256);
        b[nf][0] = pack_h2(lds_f2(ro + c0));
        b[nf][1] = pack_h2(lds_f2(ro + c1));
    }
}

template <class BS>
DI void f16_gemm(float acc[4][4][4], const __half* Ah, int lda, BS bs, int ntb,
                 int k0, int ktiles, uint32_t sbase) {
    const int t = threadIdx.x;  // 512
    const int warp = t >> 5, lane = t & 31;
    const int wm = (warp >> 2) * 64, wn = (warp & 3) * 32;
    const int gid = lane >> 2, tid = lane & 3;

#pragma unroll
    for (int mf = 0; mf < 4; mf++)
#pragma unroll
        for (int nf = 0; nf < 4; nf++)
#pragma unroll
            for (int j = 0; j < 4; j++) acc[mf][nf][j] = 0.f;

    // prologue: stages 0,1
    for (int s = 0; s < 2; s++) {
        uint32_t st = sbase + (uint32_t)s * G_STAGE;
        g_load(st, st + G_AS, Ah, lda, bs, ntb, k0 + s * 64, t);
        asm volatile("cp.async.commit_group;");
    }

    int stage = 0, nstage = 2;
    for (int kt = 0; kt < ktiles; kt++) {
        asm volatile("cp.async.wait_group 1;");
        __syncthreads();  // stage kt ready; stage being refilled was vacated by all

        if (kt + 2 < ktiles) {  // refill the stage freed 2 iterations ago
            uint32_t st = sbase + (uint32_t)nstage * G_STAGE;
            g_load(st, st + G_AS, Ah, lda, bs, ntb, k0 + (kt + 2) * 64, t);
        }
        asm volatile("cp.async.commit_group;");

        const uint32_t As = sbase + (uint32_t)stage * G_STAGE;
        const uint32_t Bs = As + G_AS;
        uint32_t a[4][4], b[4][2];
#pragma unroll
        for (int s = 0; s < 4; s++) {
            g_frag(As, Bs, wm, wn, gid, tid, s, a, b);
#pragma unroll
            for (int nf = 0; nf < 4; nf++)
#pragma unroll
                for (int mf = 0; mf < 4; mf++)
                    mma16(acc[mf][nf], a[mf], b[nf][0], b[nf][1]);
        }
        stage = (stage == 2) ? 0 : stage + 1;
        nstage = (nstage == 2) ? 0 : nstage + 1;
    }
}

// ---------- Kernel 1: fused attention + fp16 X staging ----------
__global__ void __launch_bounds__(256) attn_kernel(
    const int* __restrict__ input, const float* __restrict__ enc,
    const float* __restrict__ hidden, const float* __restrict__ emb,
    const float* __restrict__ W_energy, const float* __restrict__ b_energy)
{
    __shared__ __align__(16) float w2s[1024];
    __shared__ __align__(16) float m_acc[8][1024];
    __shared__ float red[8];
    __shared__ float s_an;
    __shared__ float m_ml[8][2];

    const int n = blockIdx.x, t = threadIdx.x;
    const int lane = t & 31, w = t >> 5;
    const float* wrow = W_energy + (size_t)1023 * 2048;
    const float* h0 = hidden + (size_t)n * HH;

    ((float4*)w2s)[t] = ((const float4*)(wrow + 1024))[t];

    float4 ha = ((const float4*)h0)[t];
    {
        float4 wa = ((const float4*)wrow)[t];
        float part = ha.x * wa.x + ha.y * wa.y + ha.z * wa.z + ha.w * wa.w;
#pragma unroll
        for (int o = 16; o > 0; o >>= 1) part += __shfl_xor_sync(0xffffffffu, part, o);
        if (lane == 0) red[w] = part;
    }
    {
        int vix = input[n];
        if (t < 128) {
            float4 e4 = ((const float4*)(emb + (size_t)vix * EE))[t];
            ((uint2*)(g_Xh + (size_t)n * KXT + 1024))[t] =
                make_uint2(pack2(e4.x, e4.y), pack2(e4.z, e4.w));
        }
        ((uint2*)(g_Xh + (size_t)n * KXT + 1536))[t] =
            make_uint2(pack2(ha.x, ha.y), pack2(ha.z, ha.w));
    }
    __syncthreads();
    if (t == 0) {
        float s = 0.f;
        for (int i = 0; i < 8; i++) s += red[i];
        s_an = s + b_energy[1023];
    }
    __syncthreads();
    const float a_n = s_an;

    float4 wv[8];
#pragma unroll
    for (int i = 0; i < 8; i++) wv[i] = ((const float4*)w2s)[i * 32 + lane];

    const float4* base = (const float4*)enc + (size_t)w * 65536 + n * 256 + lane;
    float4 v[8];
#pragma unroll
    for (int i = 0; i < 8; i++) v[i] = base[i * 32];

    float m = -1e30f, l = 0.f;
    float4 acc[8];
#pragma unroll
    for (int i = 0; i < 8; i++) acc[i] = make_float4(0.f, 0.f, 0.f, 0.f);

    for (int si = 0; si < 16; si++) {
        float4 nv[8];
        if (si < 15) {
            const float4* nb = base + (size_t)(si + 1) * 8 * 65536;
#pragma unroll
            for (int i = 0; i < 8; i++) nv[i] = nb[i * 32];
        }
        float d = 0.f;
#pragma unroll
        for (int i = 0; i < 8; i++)
            d += v[i].x * wv[i].x + v[i].y * wv[i].y + v[i].z * wv[i].z + v[i].w * wv[i].w;
#pragma unroll
        for (int o = 16; o > 0; o >>= 1) d += __shfl_xor_sync(0xffffffffu, d, o);
        float e = fmaxf(d + a_n, 0.f);
        float mn = fmaxf(m, e);
        float sc = __expf(m - mn), pw = __expf(e - mn);
        l = l * sc + pw;
#pragma unroll
        for (int i = 0; i < 8; i++) {
            acc[i].x = acc[i].x * sc + pw * v[i].x;
            acc[i].y = acc[i].y * sc + pw * v[i].y;
            acc[i].z = acc[i].z * sc + pw * v[i].z;
            acc[i].w = acc[i].w * sc + pw * v[i].w;
        }
        m = mn;
        if (si < 15) {
#pragma unroll
            for (int i = 0; i < 8; i++) v[i] = nv[i];
        }
    }
#pragma unroll
    for (int i = 0; i < 8; i++) ((float4*)&m_acc[w][0])[i * 32 + lane] = acc[i];
    if (lane == 0) { m_ml[w][0] = m; m_ml[w][1] = l; }
    __syncthreads();

    {
        float M = -1e30f;
#pragma unroll
        for (int j = 0; j < 8; j++) M = fmaxf(M, m_ml[j][0]);
        float L = 0.f;
        float wj[8];
#pragma unroll
        for (int j = 0; j < 8; j++) {
            wj[j] = __expf(m_ml[j][0] - M);
            L += wj[j] * m_ml[j][1];
        }
        float inv = 1.f / L;
        float4 c = make_float4(0.f, 0.f, 0.f, 0.f);
#pragma unroll
        for (int j = 0; j < 8; j++) {
            float4 aj = ((float4*)&m_acc[j][0])[t];
            c.x += wj[j] * aj.x; c.y += wj[j] * aj.y;
            c.z += wj[j] * aj.z; c.w += wj[j] * aj.w;
        }
        ((uint2*)(g_Xh + (size_t)n * KXT))[t] =
            make_uint2(pack2(c.x * inv, c.y * inv), pack2(c.z * inv, c.w * inv));
    }
}

// ---------- Kernel 2: gates GEMM fp16, CTA 256x128, split-K=4 ----------
__global__ void __launch_bounds__(512) gates_kernel(
    const float* __restrict__ W_ih, const float* __restrict__ W_hh)
{
    extern __shared__ __align__(16) unsigned char dynsm[];
    const int nt = blockIdx.x, sp = blockIdx.y;
    float acc[4][4][4];
    f16_gemm(acc, g_Xh, KXT, BGates{W_ih, W_hh}, nt * 128, sp * 640, 10,
             smem_u32(dynsm));

    const int t = threadIdx.x, warp = t >> 5, lane = t & 31;
    const int wm = (warp >> 2) * 64, wn = (warp & 3) * 32;
    const int gid = lane >> 2, tid = lane & 3;
    float* gbase = g_gates + (size_t)sp * NN * 4096;
#pragma unroll
    for (int mf = 0; mf < 4; mf++) {
        int row = wm + mf * 16 + gid;
#pragma unroll
        for (int nf = 0; nf < 4; nf++) {
            int col = nt * 128 + wn + nf * 8 + 2 * tid;
            *(float2*)(gbase + (size_t)row * 4096 + col) =
                make_float2(acc[mf][nf][0], acc[mf][nf][1]);
            *(float2*)(gbase + (size_t)(row + 8) * 4096 + col) =
                make_float2(acc[mf][nf][2], acc[mf][nf][3]);
        }
    }
}

// ---------- Kernel 3: LSTM elementwise ----------
__global__ void __launch_bounds__(256) lstm_kernel(
    const float* __restrict__ cell, const float* __restrict__ b_ih,
    const float* __restrict__ b_hh, float* __restrict__ out)
{
    const int idx = blockIdx.x * 256 + threadIdx.x;
    const int h = idx & 1023;
    const size_t base = (size_t)(idx >> 10) * 4096;
    float gi = 0.f, gf = 0.f, gg = 0.f, go = 0.f;
#pragma unroll
    for (int sp = 0; sp < 4; sp++) {
        const float* g = g_gates + (size_t)sp * NN * 4096 + base;
        gi += g[h]; gf += g[1024 + h]; gg += g[2048 + h]; go += g[3072 + h];
    }
    gi += b_ih[h] + b_hh[h];
    gf += b_ih[1024 + h] + b_hh[1024 + h];
    gg += b_ih[2048 + h] + b_hh[2048 + h];
    go += b_ih[3072 + h] + b_hh[3072 + h];
    float c0 = cell[idx];
    float si = 1.f / (1.f + __expf(-gi));
    float sf = 1.f / (1.f + __expf(-gf));
    float so = 1.f / (1.f + __expf(-go));
    float c1 = sf * c0 + si * tanhf(gg);
    float h1 = so * tanhf(c1);
    g_h1h[idx] = __float2half_rn(h1);    // fp16 copy for FC GEMM
    out[PRED_OFF + idx] = h1;            // exact fp32 outputs
    out[PRED_OFF + HC + idx] = c1;
}

// ---------- Kernel 4: FC GEMM fp16, CTA 256x128 ----------
__global__ void __launch_bounds__(512) fc_kernel(
    const float* __restrict__ W_fc, const float* __restrict__ b_fc,
    float* __restrict__ out)
{
    extern __shared__ __align__(16) unsigned char dynsm[];
    const int nt = blockIdx.x;
    float acc[4][4][4];
    f16_gemm(acc, g_h1h, HH, BFc{W_fc}, nt * 128, 0, 16, smem_u32(dynsm));

    const int t = threadIdx.x, warp = t >> 5, lane = t & 31;
    const int wm = (warp >> 2) * 64, wn = (warp & 3) * 32;
    const int gid = lane >> 2, tid = lane & 3;
#pragma unroll
    for (int mf = 0; mf < 4; mf++) {
        int row = wm + mf * 16 + gid;
#pragma unroll
        for (int nf = 0; nf < 4; nf++) {
            int col = nt * 128 + wn + nf * 8 + 2 * tid;
            float b0 = __ldg(b_fc + col), b1 = __ldg(b_fc + col + 1);
            *(float2*)(out + (size_t)row * VV + col) =
                make_float2(acc[mf][nf][0] + b0, acc[mf][nf][1] + b1);
            *(float2*)(out + (size_t)(row + 8) * VV + col) =
                make_float2(acc[mf][nf][2] + b0, acc[mf][nf][3] + b1);
        }
    }
}

// ---------- launch ----------
extern "C" void kernel_launch(void* const* d_in, const int* in_sizes, int n_in,
                              void* d_out, int out_size) {
    const int*   input    = (const int*)d_in[0];
    const float* enc      = (const float*)d_in[1];
    const float* hidden   = (const float*)d_in[2];
    const float* cell     = (const float*)d_in[3];
    const float* emb      = (const float*)d_in[4];
    const float* W_energy = (const float*)d_in[5];
    const float* b_energy = (const float*)d_in[6];
    const float* W_ih     = (const float*)d_in[7];
    const float* b_ih     = (const float*)d_in[8];
    const float* W_hh     = (const float*)d_in[9];
    const float* b_hh     = (const float*)d_in[10];
    const float* W_fc     = (const float*)d_in[11];
    const float* b_fc     = (const float*)d_in[12];
    float* out = (float*)d_out;

    cudaFuncSetAttribute(gates_kernel, cudaFuncAttributeMaxDynamicSharedMemorySize, G_SMEM);
    cudaFuncSetAttribute(fc_kernel, cudaFuncAttributeMaxDynamicSharedMemorySize, G_SMEM);

    attn_kernel<<<256, 256>>>(input, enc, hidden, emb, W_energy, b_energy);
    gates_kernel<<<dim3(32, 4), 512, G_SMEM>>>(W_ih, W_hh);
    lstm_kernel<<<1024, 256>>>(cell, b_ih, b_hh, out);
    fc_kernel<<<250, 512, G_SMEM>>>(W_fc, b_fc, out);
}

// round 16
// speedup vs baseline: 1.4769x; 1.4769x over previous
#include <cuda_runtime.h>
#include <cuda_fp16.h>
#include <cstdint>
#include <math.h>

#define DI __device__ __forceinline__

#define NN 256
#define HH 1024
#define EE 512
#define VV 32000
#define KXT 2560
#define PRED_OFF 8192000
#define HC (NN*HH)

__device__ __align__(16) __half g_Xh[NN * KXT];
__device__ __align__(16) float g_gates[4 * NN * 4096];
__device__ __align__(16) __half g_h1h[NN * HH];

// ---------- helpers ----------
DI uint32_t smem_u32(const void* p) {
    uint32_t a;
    asm("{ .reg .u64 t; cvta.to.shared.u64 t, %1; cvt.u32.u64 %0, t; }" : "=r"(a) : "l"(p));
    return a;
}
DI void cpa16(uint32_t s, const void* g) {
    asm volatile("cp.async.cg.shared.global [%0], [%1], 16;" :: "r"(s), "l"(g));
}
DI float2 lds_f2(uint32_t a) {
    float2 v;
    asm volatile("ld.shared.v2.f32 {%0,%1}, [%2];" : "=f"(v.x), "=f"(v.y) : "r"(a));
    return v;
}
DI void ldsm_x4(uint32_t& r0, uint32_t& r1, uint32_t& r2, uint32_t& r3, uint32_t addr) {
    asm volatile("ldmatrix.sync.aligned.m8n8.x4.shared.b16 {%0,%1,%2,%3}, [%4];"
                 : "=r"(r0), "=r"(r1), "=r"(r2), "=r"(r3) : "r"(addr));
}
DI uint32_t pack_h2(float2 v) {
    __half2 h = __floats2half2_rn(v.x, v.y);
    return *(uint32_t*)&h;
}
DI uint32_t pack2(float x, float y) {
    __half2 h = __floats2half2_rn(x, y);
    return *(uint32_t*)&h;
}
DI void mma16(float c[4], const uint32_t a[4], uint32_t b0, uint32_t b1) {
    asm volatile(
        "mma.sync.aligned.m16n8k16.row.col.f32.f16.f16.f32 "
        "{%0,%1,%2,%3}, {%4,%5,%6,%7}, {%8,%9}, {%0,%1,%2,%3};"
        : "+f"(c[0]), "+f"(c[1]), "+f"(c[2]), "+f"(c[3])
        : "r"(a[0]), "r"(a[1]), "r"(a[2]), "r"(a[3]), "r"(b0), "r"(b1));
}

// ---------- B-source functors (fp32 gmem) ----------
struct BFc {
    const float* w;
    DI const float* ptr(int r, int k) const { return w + (size_t)r * HH + k; }
};
struct BGates {
    const float* wih;
    const float* whh;
    DI const float* ptr(int r, int k) const {
        return (k < 1536) ? wih + (size_t)r * 1536 + k
                          : whh + (size_t)r * 1024 + (k - 1536);
    }
};

// =======================================================================
// fp16 GEMM core: CTA 256x128, 256 thr = 8 warps of 64x64, ktile 64
// (4 k16 steps), 3 stages, ONE barrier per iteration, A via ldmatrix,
// intra-iteration fragment double-buffering.
// A fp16: 256 rows x 144B (128B data + 16B pad -> conflict-free LDSM).
// B fp32: 128 rows x 256B, 32B-unit XOR swizzle (unit u at u^(r&7)).
// =======================================================================
#define G_AS 36864               // 256 * 144
#define G_STAGE (G_AS + 32768)   // + B 128 * 256
#define G_SMEM (3 * G_STAGE)     // 208896

template <class BS>
DI void g_load(uint32_t As, uint32_t Bs, const __half* Ah, int lda, BS bs,
               int ntb, int kg, int t) {
#pragma unroll
    for (int i = 0; i < 8; i++) {  // A: 256 rows x 8 chunks of 16B
        int idx = i * 256 + t, r = idx >> 3, c = idx & 7;
        cpa16(As + (uint32_t)(r * 144 + c * 16),
              (const char*)Ah + (size_t)r * lda * 2 + (size_t)kg * 2 + c * 16);
    }
#pragma unroll
    for (int i = 0; i < 8; i++) {  // B: 128 rows x 16 chunks of 16B
        int idx = i * 256 + t, r = idx >> 4, cc = idx & 15;
        cpa16(Bs + (uint32_t)(r * 256 + (((cc >> 1) ^ (r & 7)) << 5) + (cc & 1) * 16),
              bs.ptr(ntb + r, kg + cc * 4));
    }
}

// A frags via ldmatrix: lane -> row (lane&15), byte-col (lane>>4)*16
DI void g_frag(uint32_t As, uint32_t Bs, int wm, int wn, int lane, int gid,
               int tid, int s, uint32_t a[4][4], uint32_t b[8][2]) {
    const uint32_t arow = (uint32_t)(wm + (lane & 15));
    const uint32_t acol = (uint32_t)(s * 32 + ((lane >> 4) << 4));
#pragma unroll
    for (int mf = 0; mf < 4; mf++) {
        uint32_t ad = As + (arow + mf * 16) * 144 + acol;
        ldsm_x4(a[mf][0], a[mf][1], a[mf][2], a[mf][3], ad);
    }
    const uint32_t c0 = (uint32_t)((((2 * s) ^ gid) << 5) + tid * 8);
    const uint32_t c1 = (uint32_t)((((2 * s + 1) ^ gid) << 5) + tid * 8);
#pragma unroll
    for (int nf = 0; nf < 8; nf++) {
        uint32_t ro = Bs + (uint32_t)((wn + nf * 8 + gid) * 256);
        b[nf][0] = pack_h2(lds_f2(ro + c0));
        b[nf][1] = pack_h2(lds_f2(ro + c1));
    }
}

template <class BS>
DI void f16_gemm(float acc[4][8][4], const __half* Ah, int lda, BS bs, int ntb,
                 int k0, int ktiles, uint32_t sbase) {
    const int t = threadIdx.x;  // 256
    const int warp = t >> 5, lane = t & 31;
    const int wm = (warp >> 1) * 64, wn = (warp & 1) * 64;
    const int gid = lane >> 2, tid = lane & 3;

#pragma unroll
    for (int mf = 0; mf < 4; mf++)
#pragma unroll
        for (int nf = 0; nf < 8; nf++)
#pragma unroll
            for (int j = 0; j < 4; j++) acc[mf][nf][j] = 0.f;

    // prologue: stages 0,1
    for (int s = 0; s < 2; s++) {
        uint32_t st = sbase + (uint32_t)s * G_STAGE;
        g_load(st, st + G_AS, Ah, lda, bs, ntb, k0 + s * 64, t);
        asm volatile("cp.async.commit_group;");
    }

    int stage = 0, nstage = 2;
    for (int kt = 0; kt < ktiles; kt++) {
        asm volatile("cp.async.wait_group 1;");
        __syncthreads();  // stage kt ready; refill target was vacated by all

        if (kt + 2 < ktiles) {
            uint32_t st = sbase + (uint32_t)nstage * G_STAGE;
            g_load(st, st + G_AS, Ah, lda, bs, ntb, k0 + (kt + 2) * 64, t);
        }
        asm volatile("cp.async.commit_group;");

        const uint32_t As = sbase + (uint32_t)stage * G_STAGE;
        const uint32_t Bs = As + G_AS;

        uint32_t a[2][4][4], b[2][8][2];
        g_frag(As, Bs, wm, wn, lane, gid, tid, 0, a[0], b[0]);
#pragma unroll
        for (int s = 0; s < 4; s++) {
            const int cur = s & 1, nxt = cur ^ 1;
            if (s < 3) g_frag(As, Bs, wm, wn, lane, gid, tid, s + 1, a[nxt], b[nxt]);
#pragma unroll
            for (int nf = 0; nf < 8; nf++)
#pragma unroll
                for (int mf = 0; mf < 4; mf++)
                    mma16(acc[mf][nf], a[cur][mf], b[cur][nf][0], b[cur][nf][1]);
        }
        stage = (stage == 2) ? 0 : stage + 1;
        nstage = (nstage == 2) ? 0 : nstage + 1;
    }
}

// ---------- Kernel 1: fused attention + fp16 X staging ----------
__global__ void __launch_bounds__(256) attn_kernel(
    const int* __restrict__ input, const float* __restrict__ enc,
    const float* __restrict__ hidden, const float* __restrict__ emb,
    const float* __restrict__ W_energy, const float* __restrict__ b_energy)
{
    __shared__ __align__(16) float w2s[1024];
    __shared__ __align__(16) float m_acc[8][1024];
    __shared__ float red[8];
    __shared__ float s_an;
    __shared__ float m_ml[8][2];

    const int n = blockIdx.x, t = threadIdx.x;
    const int lane = t & 31, w = t >> 5;
    const float* wrow = W_energy + (size_t)1023 * 2048;
    const float* h0 = hidden + (size_t)n * HH;

    ((float4*)w2s)[t] = ((const float4*)(wrow + 1024))[t];

    float4 ha = ((const float4*)h0)[t];
    {
        float4 wa = ((const float4*)wrow)[t];
        float part = ha.x * wa.x + ha.y * wa.y + ha.z * wa.z + ha.w * wa.w;
#pragma unroll
        for (int o = 16; o > 0; o >>= 1) part += __shfl_xor_sync(0xffffffffu, part, o);
        if (lane == 0) red[w] = part;
    }
    {
        int vix = input[n];
        if (t < 128) {
            float4 e4 = ((const float4*)(emb + (size_t)vix * EE))[t];
            ((uint2*)(g_Xh + (size_t)n * KXT + 1024))[t] =
                make_uint2(pack2(e4.x, e4.y), pack2(e4.z, e4.w));
        }
        ((uint2*)(g_Xh + (size_t)n * KXT + 1536))[t] =
            make_uint2(pack2(ha.x, ha.y), pack2(ha.z, ha.w));
    }
    __syncthreads();
    if (t == 0) {
        float s = 0.f;
        for (int i = 0; i < 8; i++) s += red[i];
        s_an = s + b_energy[1023];
    }
    __syncthreads();
    const float a_n = s_an;

    float4 wv[8];
#pragma unroll
    for (int i = 0; i < 8; i++) wv[i] = ((const float4*)w2s)[i * 32 + lane];

    const float4* base = (const float4*)enc + (size_t)w * 65536 + n * 256 + lane;
    float4 v[8];
#pragma unroll
    for (int i = 0; i < 8; i++) v[i] = base[i * 32];

    float m = -1e30f, l = 0.f;
    float4 acc[8];
#pragma unroll
    for (int i = 0; i < 8; i++) acc[i] = make_float4(0.f, 0.f, 0.f, 0.f);

    for (int si = 0; si < 16; si++) {
        float4 nv[8];
        if (si < 15) {
            const float4* nb = base + (size_t)(si + 1) * 8 * 65536;
#pragma unroll
            for (int i = 0; i < 8; i++) nv[i] = nb[i * 32];
        }
        float d = 0.f;
#pragma unroll
        for (int i = 0; i < 8; i++)
            d += v[i].x * wv[i].x + v[i].y * wv[i].y + v[i].z * wv[i].z + v[i].w * wv[i].w;
#pragma unroll
        for (int o = 16; o > 0; o >>= 1) d += __shfl_xor_sync(0xffffffffu, d, o);
        float e = fmaxf(d + a_n, 0.f);
        float mn = fmaxf(m, e);
        float sc = __expf(m - mn), pw = __expf(e - mn);
        l = l * sc + pw;
#pragma unroll
        for (int i = 0; i < 8; i++) {
            acc[i].x = acc[i].x * sc + pw * v[i].x;
            acc[i].y = acc[i].y * sc + pw * v[i].y;
            acc[i].z = acc[i].z * sc + pw * v[i].z;
            acc[i].w = acc[i].w * sc + pw * v[i].w;
        }
        m = mn;
        if (si < 15) {
#pragma unroll
            for (int i = 0; i < 8; i++) v[i] = nv[i];
        }
    }
#pragma unroll
    for (int i = 0; i < 8; i++) ((float4*)&m_acc[w][0])[i * 32 + lane] = acc[i];
    if (lane == 0) { m_ml[w][0] = m; m_ml[w][1] = l; }
    __syncthreads();

    {
        float M = -1e30f;
#pragma unroll
        for (int j = 0; j < 8; j++) M = fmaxf(M, m_ml[j][0]);
        float L = 0.f;
        float wj[8];
#pragma unroll
        for (int j = 0; j < 8; j++) {
            wj[j] = __expf(m_ml[j][0] - M);
            L += wj[j] * m_ml[j][1];
        }
        float inv = 1.f / L;
        float4 c = make_float4(0.f, 0.f, 0.f, 0.f);
#pragma unroll
        for (int j = 0; j < 8; j++) {
            float4 aj = ((float4*)&m_acc[j][0])[t];
            c.x += wj[j] * aj.x; c.y += wj[j] * aj.y;
            c.z += wj[j] * aj.z; c.w += wj[j] * aj.w;
        }
        ((uint2*)(g_Xh + (size_t)n * KXT))[t] =
            make_uint2(pack2(c.x * inv, c.y * inv), pack2(c.z * inv, c.w * inv));
    }
}

// ---------- Kernel 2: gates GEMM fp16, CTA 256x128, split-K=4 ----------
__global__ void __launch_bounds__(256) gates_kernel(
    const float* __restrict__ W_ih, const float* __restrict__ W_hh)
{
    extern __shared__ __align__(16) unsigned char dynsm[];
    const int nt = blockIdx.x, sp = blockIdx.y;
    float acc[4][8][4];
    f16_gemm(acc, g_Xh, KXT, BGates{W_ih, W_hh}, nt * 128, sp * 640, 10,
             smem_u32(dynsm));

    const int t = threadIdx.x, warp = t >> 5, lane = t & 31;
    const int wm = (warp >> 1) * 64, wn = (warp & 1) * 64;
    const int gid = lane >> 2, tid = lane & 3;
    float* gbase = g_gates + (size_t)sp * NN * 4096;
#pragma unroll
    for (int mf = 0; mf < 4; mf++) {
        int row = wm + mf * 16 + gid;
#pragma unroll
        for (int nf = 0; nf < 8; nf++) {
            int col = nt * 128 + wn + nf * 8 + 2 * tid;
            *(float2*)(gbase + (size_t)row * 4096 + col) =
                make_float2(acc[mf][nf][0], acc[mf][nf][1]);
            *(float2*)(gbase + (size_t)(row + 8) * 4096 + col) =
                make_float2(acc[mf][nf][2], acc[mf][nf][3]);
        }
    }
}

// ---------- Kernel 3: LSTM elementwise ----------
__global__ void __launch_bounds__(256) lstm_kernel(
    const float* __restrict__ cell, const float* __restrict__ b_ih,
    const float* __restrict__ b_hh, float* __restrict__ out)
{
    const int idx = blockIdx.x * 256 + threadIdx.x;
    const int h = idx & 1023;
    const size_t base = (size_t)(idx >> 10) * 4096;
    float gi = 0.f, gf = 0.f, gg = 0.f, go = 0.f;
#pragma unroll
    for (int sp = 0; sp < 4; sp++) {
        const float* g = g_gates + (size_t)sp * NN * 4096 + base;
        gi += g[h]; gf += g[1024 + h]; gg += g[2048 + h]; go += g[3072 + h];
    }
    gi += b_ih[h] + b_hh[h];
    gf += b_ih[1024 + h] + b_hh[1024 + h];
    gg += b_ih[2048 + h] + b_hh[2048 + h];
    go += b_ih[3072 + h] + b_hh[3072 + h];
    float c0 = cell[idx];
    float si = 1.f / (1.f + __expf(-gi));
    float sf = 1.f / (1.f + __expf(-gf));
    float so = 1.f / (1.f + __expf(-go));
    float c1 = sf * c0 + si * tanhf(gg);
    float h1 = so * tanhf(c1);
    g_h1h[idx] = __float2half_rn(h1);    // fp16 copy for FC GEMM
    out[PRED_OFF + idx] = h1;            // exact fp32 outputs
    out[PRED_OFF + HC + idx] = c1;
}

// ---------- Kernel 4: FC GEMM fp16, CTA 256x128 ----------
__global__ void __launch_bounds__(256) fc_kernel(
    const float* __restrict__ W_fc, const float* __restrict__ b_fc,
    float* __restrict__ out)
{
    extern __shared__ __align__(16) unsigned char dynsm[];
    const int nt = blockIdx.x;
    float acc[4][8][4];
    f16_gemm(acc, g_h1h, HH, BFc{W_fc}, nt * 128, 0, 16, smem_u32(dynsm));

    const int t = threadIdx.x, warp = t >> 5, lane = t & 31;
    const int wm = (warp >> 1) * 64, wn = (warp & 1) * 64;
    const int gid = lane >> 2, tid = lane & 3;
#pragma unroll
    for (int mf = 0; mf < 4; mf++) {
        int row = wm + mf * 16 + gid;
#pragma unroll
        for (int nf = 0; nf < 8; nf++) {
            int col = nt * 128 + wn + nf * 8 + 2 * tid;
            float b0 = __ldg(b_fc + col), b1 = __ldg(b_fc + col + 1);
            *(float2*)(out + (size_t)row * VV + col) =
                make_float2(acc[mf][nf][0] + b0, acc[mf][nf][1] + b1);
            *(float2*)(out + (size_t)(row + 8) * VV + col) =
                make_float2(acc[mf][nf][2] + b0, acc[mf][nf][3] + b1);
        }
    }
}

// ---------- launch ----------
extern "C" void kernel_launch(void* const* d_in, const int* in_sizes, int n_in,
                              void* d_out, int out_size) {
    const int*   input    = (const int*)d_in[0];
    const float* enc      = (const float*)d_in[1];
    const float* hidden   = (const float*)d_in[2];
    const float* cell     = (const float*)d_in[3];
    const float* emb      = (const float*)d_in[4];
    const float* W_energy = (const float*)d_in[5];
    const float* b_energy = (const float*)d_in[6];
    const float* W_ih     = (const float*)d_in[7];
    const float* b_ih     = (const float*)d_in[8];
    const float* W_hh     = (const float*)d_in[9];
    const float* b_hh     = (const float*)d_in[10];
    const float* W_fc     = (const float*)d_in[11];
    const float* b_fc     = (const float*)d_in[12];
    float* out = (float*)d_out;

    cudaFuncSetAttribute(gates_kernel, cudaFuncAttributeMaxDynamicSharedMemorySize, G_SMEM);
    cudaFuncSetAttribute(fc_kernel, cudaFuncAttributeMaxDynamicSharedMemorySize, G_SMEM);

    attn_kernel<<<256, 256>>>(input, enc, hidden, emb, W_energy, b_energy);
    gates_kernel<<<dim3(32, 4), 256, G_SMEM>>>(W_ih, W_hh);
    lstm_kernel<<<1024, 256>>>(cell, b_ih, b_hh, out);
    fc_kernel<<<250, 256, G_SMEM>>>(W_fc, b_fc, out);
}